// round 14
// baseline (speedup 1.0000x reference)
#include <cuda_runtime.h>
#include <cstdint>
#include <cstdio>

// Batched greedy nearest-neighbor (B<=64, N=1000). Output float32:
//   [ pred (B,N) | pred_len (B,) ].
// R12: chain probe collapsed to LDS->LDS->REDUX (visited bitset mirrored in
// SMEM; single __reduce_min_sync picks the first-unvisited sorted candidate).
// R8 topk (threshold compaction + tournament) kept unchanged.

#define GN   1000
#define GK   24
#define MAXB 64

__device__ __align__(16) unsigned short g_cand[(size_t)MAXB * GN * GK]; // 3MB

// --------------------------------------------------------------------------
// slow-path helper: per-lane exact min key over 32 owned elems minus `sel`
// ownership: lane t owns idx = c*128 + 4t + j (c<8, j<4); kb[e], e = c*4+j
__device__ __forceinline__ unsigned long long
extract_min(const unsigned* kb, unsigned sel, int t)
{
    unsigned long long best = ~0ull;
#pragma unroll
    for (int e = 0; e < 32; ++e) {
        const unsigned idx = (unsigned)((e >> 2) * 128 + 4 * t + (e & 3));
        unsigned long long k = ((unsigned long long)kb[e] << 32) | idx;
        if ((sel >> e) & 1u) k = ~0ull;
        best = (k < best) ? k : best;
    }
    return best;
}

__device__ __forceinline__ void cswap(unsigned long long& a, unsigned long long& b)
{
    const unsigned long long lo = (a < b) ? a : b;
    b = (a < b) ? b : a;
    a = lo;
}

// ---- preprocess: one warp per row -> 24 smallest indices, sorted exactly ---
__global__ void __launch_bounds__(256)
topk_kernel(const float* __restrict__ dist, int rows)
{
    __shared__ unsigned long long comp[8][128];          // 8KB / CTA
    const int wi = threadIdx.x >> 5;
    const int w  = blockIdx.x * 8 + wi;
    if (w >= rows) return;
    const int t = threadIdx.x & 31;
    const unsigned FULL = 0xffffffffu;
    constexpr float T_F = 0.0625f;                        // E[cnt]=62.5, sd=7.7

    const float* __restrict__ row = dist + (size_t)w * GN;
    unsigned short* __restrict__ crow = g_cand + (size_t)w * GK;

    float4 v[8];
#pragma unroll
    for (int c = 0; c < 8; ++c) {
        const int base = c * 128 + 4 * t;
        if (base + 3 < GN) v[c] = *reinterpret_cast<const float4*>(row + base);
        else               v[c] = make_float4(1e6f, 1e6f, 1e6f, 1e6f);
    }

    int cnt = 0;
#pragma unroll
    for (int c = 0; c < 8; ++c) {
        const float* vp = &v[c].x;
#pragma unroll
        for (int j = 0; j < 4; ++j) cnt += (vp[j] < T_F) ? 1 : 0;
    }
    const int total = __reduce_add_sync(FULL, (unsigned)cnt);

    if (total >= GK && total <= 128) {
        // fast path: compact keys < T, select 24 smallest exactly
        unsigned scan = (unsigned)cnt;
#pragma unroll
        for (int off = 1; off < 32; off <<= 1) {
            const unsigned n = __shfl_up_sync(FULL, scan, off);
            if (t >= off) scan += n;
        }
        unsigned ptr = scan - (unsigned)cnt;
        unsigned long long* cbuf = comp[wi];
#pragma unroll
        for (int c = 0; c < 8; ++c) {
            const int base = c * 128 + 4 * t;
            const float* vp = &v[c].x;
#pragma unroll
            for (int j = 0; j < 4; ++j) {
                if (vp[j] < T_F) {
                    cbuf[ptr++] = ((unsigned long long)__float_as_uint(vp[j]) << 32)
                                | (unsigned)(base + j);
                }
            }
        }
        __syncwarp();

        unsigned long long e0 = (t < total)      ? cbuf[t]      : ~0ull;
        unsigned long long e1 = (t + 32 < total) ? cbuf[t + 32] : ~0ull;
        unsigned long long e2 = (t + 64 < total) ? cbuf[t + 64] : ~0ull;
        unsigned long long e3 = (t + 96 < total) ? cbuf[t + 96] : ~0ull;
        cswap(e0, e1); cswap(e2, e3); cswap(e0, e2); cswap(e1, e3); cswap(e1, e2);

        unsigned long long cand = e0;
#pragma unroll
        for (int rnd = 0; rnd < GK; ++rnd) {
            const unsigned hi   = (unsigned)(cand >> 32);
            const unsigned ghi  = __reduce_min_sync(FULL, hi);
            const unsigned mylo = (hi == ghi) ? (unsigned)cand : 0xffffffffu;
            const unsigned glo  = __reduce_min_sync(FULL, mylo);
            if (t == 0) crow[rnd] = (unsigned short)glo;
            if (hi == ghi && (unsigned)cand == glo) {
                e0 = e1; e1 = e2; e2 = e3; e3 = ~0ull;
                cand = e0;
            }
        }
    } else {
        // rare exact retry (~2e-7/row)
        unsigned kb[32];
#pragma unroll
        for (int c = 0; c < 8; ++c) {
            const int base = c * 128 + 4 * t;
            const float* vp = &v[c].x;
#pragma unroll
            for (int j = 0; j < 4; ++j)
                kb[c * 4 + j] = (base + 3 < GN) ? __float_as_uint(vp[j])
                                                : 0xffffffffu;
        }
        unsigned long long top[4];
        unsigned pm = 0;
#pragma unroll
        for (int p = 0; p < 4; ++p) {
            top[p] = extract_min(kb, pm, t);
            const unsigned idx = (unsigned)top[p];
            pm |= 1u << (((idx >> 7) << 2) | (idx & 3));
        }
        unsigned sel = 0;
        int ptr = 0;
        unsigned long long cand = top[0];
        for (int rnd = 0; rnd < GK; ++rnd) {
            const unsigned hi   = (unsigned)(cand >> 32);
            const unsigned ghi  = __reduce_min_sync(FULL, hi);
            const unsigned mylo = (hi == ghi) ? (unsigned)cand : 0xffffffffu;
            const unsigned gidx = __reduce_min_sync(FULL, mylo);
            if (t == 0) crow[rnd] = (unsigned short)gidx;
            if (hi == ghi && (unsigned)cand == gidx) {
                sel |= 1u << (((gidx >> 7) << 2) | (gidx & 3));
                ++ptr;
                cand = (ptr < 4) ? top[ptr] : extract_min(kb, sel, t);
            }
        }
    }
}

// ---- exact fallback: full-row masked argmin (lane t owns [32t, 32t+32)) ---
__device__ __forceinline__ int
fb_scan(const float* __restrict__ row, unsigned vis, int t)
{
    const unsigned FULL = 0xffffffffu;
    unsigned long long best = ~0ull;
#pragma unroll
    for (int j = 0; j < 8; ++j) {
        const int base = 32 * t + 4 * j;
        if (base + 3 < GN) {
            const float4 v = *reinterpret_cast<const float4*>(row + base);
            const float* vp = &v.x;
#pragma unroll
            for (int q = 0; q < 4; ++q) {
                const int e = 4 * j + q;
                const unsigned fb = ((vis >> e) & 1u) ? 0xffffffffu
                                                      : __float_as_uint(vp[q]);
                const unsigned long long k =
                    ((unsigned long long)fb << 32) | (unsigned)(base + q);
                best = (k < best) ? k : best;
            }
        }
    }
    const unsigned hi   = (unsigned)(best >> 32);
    const unsigned ghi  = __reduce_min_sync(FULL, hi);
    const unsigned mylo = (hi == ghi) ? (unsigned)best : 0xffffffffu;
    return (int)__reduce_min_sync(FULL, mylo);
}

// ---- chain: one warp per batch; probe = LDS -> LDS -> REDUX ---------------
__global__ void __launch_bounds__(32, 1)
chain_kernel(const float* __restrict__ dist,
             const void* __restrict__ mask_raw,
             const int* __restrict__ start,
             float* __restrict__ out,
             int B, int out_size)
{
    __shared__ __align__(16) unsigned short s_cand[GN * GK + 32]; // pad: lanes
    __shared__ unsigned s_vis[32];                                // t>=GK read OOB
    const int b = blockIdx.x;
    const int t = threadIdx.x;
    const unsigned FULL = 0xffffffffu;

    // stage this batch's candidate table (48KB, uint4 copies)
    {
        const uint4* src = reinterpret_cast<const uint4*>(
            g_cand + (size_t)b * GN * GK);
        uint4* dst = reinterpret_cast<uint4*>(s_cand);
        for (int i = t; i < (GN * GK * 2) / 16; i += 32) dst[i] = src[i];
    }

    // sniff mask wire dtype (first 512 bytes)
    const uint8_t* mbp = (const uint8_t*)mask_raw;
    bool weird = false, offnz = false;
#pragma unroll
    for (int i = 0; i < 16; ++i) {
        const int p = t * 16 + i;
        const uint8_t v = mbp[p];
        if (v > 1) weird = true;
        if (v != 0 && (p & 3) != 0) offnz = true;
    }
    const int mode = __ballot_sync(FULL, weird) ? 2
                   : (__ballot_sync(FULL, offnz) ? 1 : 0);

    // visited bitset: register word t covers idx [32t,32t+32); mirrored in smem
    unsigned visited = 0;
    const size_t moff = (size_t)b * GN;
#pragma unroll
    for (int j = 0; j < 32; ++j) {
        const int idx = 32 * t + j;
        bool m = true;
        if (idx < GN) {
            if (mode == 0)      m = (((const int*)mask_raw)[moff + idx] != 0);
            else if (mode == 1) m = (((const uint8_t*)mask_raw)[moff + idx] != 0);
            else                m = (((const float*)mask_raw)[moff + idx] != 0.0f);
        }
        if (m) visited |= 1u << j;
    }
    const int rem = __reduce_add_sync(FULL, __popc(~visited));  // pred_len
    s_vis[t] = visited;
    __syncwarp();                                   // s_cand + s_vis ready

    const float* __restrict__ D = dist + (size_t)b * GN * GN;
    float* __restrict__ pred = out + (size_t)b * GN;
    int point = start[b];
    if (point < 0 || point >= GN) point = 0;

    const unsigned short* __restrict__ cl = s_cand + t;

    for (int step = 0; step < rem; ++step) {
        // rank-t candidate of current row, then visited lookup (both LDS)
        const unsigned cc = (unsigned)cl[point * GK];
        const unsigned vw = s_vis[cc >> 5];
        // key = (rank<<10)|idx for unvisited probe lanes, else BIG
        unsigned key = 0xffffffffu;
        if (t < GK && !((vw >> (cc & 31)) & 1u)) key = ((unsigned)t << 10) | cc;
        const unsigned gk = __reduce_min_sync(FULL, key);

        int g;
        if (gk != 0xffffffffu) {
            g = (int)(gk & 1023u);                  // first unvisited = argmin
        } else {
            g = fb_scan(D + (size_t)point * GN, visited, t);  // exact, rare
        }

        if (t == (g >> 5)) {                        // owner updates both copies
            visited |= 1u << (g & 31);
            s_vis[t] = visited;
        }
        if (t == 0) pred[step] = (float)g;
        point = g;
        __syncwarp();                               // publish s_vis update
    }

    // pad tail + pred_len (guarded), as floats
    for (int s = rem + t; s < GN; s += 32) pred[s] = (float)GN;
    if (t == 0 && (size_t)B * GN + b < (size_t)out_size)
        out[(size_t)B * GN + b] = (float)rem;
}

extern "C" void kernel_launch(void* const* d_in, const int* in_sizes, int n_in,
                              void* d_out, int out_size)
{
    fprintf(stderr, "[greedy] n_in=%d sizes:", n_in);
    for (int i = 0; i < n_in && i < 8; ++i) fprintf(stderr, " %d", in_sizes[i]);
    fprintf(stderr, " out_size=%d\n", out_size);

    // identify inputs by element count, descending
    int order[8];
    const int m = (n_in < 8) ? n_in : 8;
    for (int i = 0; i < m; ++i) order[i] = i;
    for (int i = 0; i < m; ++i)
        for (int j = i + 1; j < m; ++j)
            if (in_sizes[order[j]] > in_sizes[order[i]]) {
                int tmp = order[i]; order[i] = order[j]; order[j] = tmp;
            }

    const float* dist  = (const float*)d_in[order[0]];
    const void*  mask  = d_in[order[1]];
    const int*   start = (const int*)d_in[order[2]];
    float*       out   = (float*)d_out;

    long long cand[4];
    cand[0] = in_sizes[order[2]];
    cand[1] = in_sizes[order[1]] / GN;
    cand[2] = in_sizes[order[0]] / ((long long)GN * GN);
    cand[3] = out_size / GN;
    long long B = cand[0];
    for (int i = 1; i < 4; ++i)
        if (cand[i] >= 1 && cand[i] < B) B = cand[i];
    if (B < 1) B = 1;
    if (B > MAXB) B = MAXB;

    const int rows = (int)B * GN;
    topk_kernel<<<(rows + 7) / 8, 256>>>(dist, rows);
    chain_kernel<<<(int)B, 32>>>(dist, mask, start, out, (int)B, out_size);
}